// round 1
// baseline (speedup 1.0000x reference)
#include <cuda_runtime.h>
#include <cstdint>
#include <math.h>

// IMLE sampler: out[s,b,n] = 1 if (logits[b,n] + Gumbel(noise[s,b,n])) is in
// that row's top-k, else 0.  S=16, B=128, N=16384, k=32.
//
// One CTA per row. Fast __logf pass for everything (HBM-bound), exact
// double-precision-log recompute for only the few candidates near the
// threshold; ties broken by lowest index to match jax.lax.top_k.

#define NCOLS   16384
#define THREADS 1024
#define CHUNKS  4          // float4 chunks per thread: 4*4*1024 = 16384
#define HBINS   4096       // 12-bit key prefix histogram
#define CAP     2048       // candidate list capacity (typ. ~40-150 used)
#define MARGIN  0.25f      // >> worst-case fast-log error near the boundary

__device__ __forceinline__ unsigned f2k(float f) {
    unsigned b = __float_as_uint(f);
    return b ^ ((unsigned)((int)b >> 31) | 0x80000000u);
}
__device__ __forceinline__ float k2f(unsigned k) {
    unsigned b = (k & 0x80000000u) ? (k ^ 0x80000000u) : ~k;
    return __uint_as_float(b);
}

// Correctly-rounded f32 log chain via double (immune to --use_fast_math):
// mimics reference float32 op-by-op: t1=log(u); t3=log(-t1); p=logit-t3
__device__ __forceinline__ float exact_perturb(float u, float lg) {
    float t1 = (float)log((double)u);
    float t3 = (float)log((double)(-t1));
    return lg + (-t3);
}

__global__ __launch_bounds__(THREADS)
void imle_topk_kernel(const float* __restrict__ logits,
                      const float* __restrict__ noise,
                      const int* __restrict__ kptr,
                      float* __restrict__ out,
                      int Brows)
{
    __shared__ unsigned hist[HBINS];
    __shared__ int wsum[32];
    __shared__ int wsuf[32];
    __shared__ int sh_D;
    __shared__ int sh_cnt;
    __shared__ int   sh_cidx[CAP];
    __shared__ float sh_cval[CAP];

    const int tid  = threadIdx.x;
    const int lane = tid & 31;
    const int warp = tid >> 5;
    const int row  = blockIdx.x;
    const size_t rowoff = (size_t)row * NCOLS;
    const size_t logoff = (size_t)(row % Brows) * NCOLS;

    for (int i = tid; i < HBINS; i += THREADS) hist[i] = 0u;
    if (tid == 0) sh_cnt = 0;
    __syncthreads();

    const float4* n4 = reinterpret_cast<const float4*>(noise  + rowoff);
    const float4* l4 = reinterpret_cast<const float4*>(logits + logoff);
    float4*       o4 = reinterpret_cast<float4*>(out + rowoff);

    unsigned keys[CHUNKS * 4];
    const float4 zero4 = make_float4(0.f, 0.f, 0.f, 0.f);

    // Phase 1: stream noise, compute fast perturbed keys, histogram top-12
    // bits, and zero-fill the output (overlaps read+write bandwidth).
    #pragma unroll
    for (int c = 0; c < CHUNKS; ++c) {
        int v = tid + c * THREADS;           // float4 index within row
        float4 u = __ldcs(&n4[v]);           // streaming: read-once
        float4 l = __ldg(&l4[v]);            // cached: reused across S samples
        float p0 = l.x - __logf(-__logf(u.x));
        float p1 = l.y - __logf(-__logf(u.y));
        float p2 = l.z - __logf(-__logf(u.z));
        float p3 = l.w - __logf(-__logf(u.w));
        unsigned k0 = f2k(p0), k1 = f2k(p1), k2 = f2k(p2), k3 = f2k(p3);
        keys[c*4+0] = k0; keys[c*4+1] = k1;
        keys[c*4+2] = k2; keys[c*4+3] = k3;
        atomicAdd(&hist[k0 >> 20], 1u);
        atomicAdd(&hist[k1 >> 20], 1u);
        atomicAdd(&hist[k2 >> 20], 1u);
        atomicAdd(&hist[k3 >> 20], 1u);
        __stcs(&o4[v], zero4);
    }
    __syncthreads();

    int kk = kptr ? *kptr : 32;
    if (kk < 1) kk = 1;
    if (kk > NCOLS) kk = NCOLS;

    // Phase 2: suffix-scan the histogram (thread t owns bins 4t..4t+3) to
    // find bin D containing the kk-th largest fast key.
    int v4 = (int)(hist[4*tid] + hist[4*tid+1] + hist[4*tid+2] + hist[4*tid+3]);
    int s = v4;                              // becomes suffix-incl within warp
    #pragma unroll
    for (int off = 1; off < 32; off <<= 1) {
        int o = __shfl_down_sync(0xFFFFFFFFu, s, off);
        if (lane + off < 32) s += o;
    }
    if (lane == 0) wsum[warp] = s;           // lane0 suffix = warp total
    __syncthreads();
    if (warp == 0) {
        int ws = wsum[lane];
        int t2 = ws;
        #pragma unroll
        for (int off = 1; off < 32; off <<= 1) {
            int o = __shfl_down_sync(0xFFFFFFFFu, t2, off);
            if (lane + off < 32) t2 += o;
        }
        wsuf[lane] = t2 - ws;                // sum over warps strictly above
    }
    __syncthreads();
    int S_incl = wsuf[warp] + s;             // count of keys in bins >= 4*tid
    int S_excl = S_incl - v4;                // count in bins >  4*tid+3
    if (S_incl >= kk && S_excl < kk) {       // exactly one thread matches
        int cum = S_excl;
        #pragma unroll
        for (int b = 3; b >= 0; --b) {
            cum += (int)hist[4*tid + b];
            if (cum >= kk) { sh_D = 4*tid + b; break; }
        }
    }
    __syncthreads();

    // Phase 3/4: candidate collection (fast key >= lower-edge(D) - MARGIN)
    float edge = k2f(((unsigned)sh_D) << 20);
    unsigned thrk = f2k(edge - MARGIN);

    #pragma unroll
    for (int c = 0; c < CHUNKS; ++c) {
        #pragma unroll
        for (int j = 0; j < 4; ++j) {
            if (keys[c*4+j] >= thrk) {
                int pos = atomicAdd(&sh_cnt, 1);
                if (pos < CAP) sh_cidx[pos] = 4*(tid + c*THREADS) + j;
            }
        }
    }
    __syncthreads();
    int cnt = sh_cnt < CAP ? sh_cnt : CAP;

    // Phase 5: exact recompute for candidates only (L2-hot reloads)
    for (int i = tid; i < cnt; i += THREADS) {
        int idx = sh_cidx[i];
        float u  = noise[rowoff + idx];
        float lg = logits[logoff + idx];
        sh_cval[i] = exact_perturb(u, lg);
    }
    __syncthreads();

    // Phase 6: exact O(c^2) rank with jax top_k tie-break (lowest index wins)
    for (int i = tid; i < cnt; i += THREADS) {
        float pi = sh_cval[i];
        int   ii = sh_cidx[i];
        int r = 0;
        for (int j = 0; j < cnt; ++j) {
            float pj = sh_cval[j];
            r += (pj > pi) || (pj == pi && sh_cidx[j] < ii);
        }
        if (r < kk) out[rowoff + ii] = 1.0f;
    }
}

extern "C" void kernel_launch(void* const* d_in, const int* in_sizes, int n_in,
                              void* d_out, int out_size) {
    // Identify inputs by size: k is the scalar, noise is the largest,
    // logits is the remaining tensor.
    int iK = -1, iU = -1, iL = -1;
    for (int i = 0; i < n_in; ++i)
        if (in_sizes[i] == 1) { iK = i; }
    long best = -1;
    for (int i = 0; i < n_in; ++i) {
        if (i == iK) continue;
        if ((long)in_sizes[i] > best) { best = in_sizes[i]; iU = i; }
    }
    for (int i = 0; i < n_in; ++i)
        if (i != iK && i != iU) { iL = i; break; }

    const float* logits = (const float*)d_in[iL];
    const float* noise  = (const float*)d_in[iU];
    const int*   kptr   = (iK >= 0) ? (const int*)d_in[iK] : nullptr;
    float* out = (float*)d_out;

    int rows  = in_sizes[iU] / NCOLS;   // S*B = 2048
    int Brows = in_sizes[iL] / NCOLS;   // B   = 128

    imle_topk_kernel<<<rows, THREADS>>>(logits, noise, kptr, out, Brows);
}